// round 7
// baseline (speedup 1.0000x reference)
#include <cuda_runtime.h>
#include <cuda_fp16.h>
#include <cstdint>

#define NPX      65536
#define KCODES   1024
#define DDIM     256
#define HW       4096
#define TILE_PX  128
#define CHUNK    64
#define NCHUNK   16
#define ZQ_ELEMS 16777216

// ---- smem layout (bytes) ----
#define ZH_OFF   0            // 65536: zh [c2:128][px:128] u32(half2)
#define EH_OFF   65536        // 2 x 32768: eh [c2:128][k:64] u32(half2)
#define EH_BYTES 32768
#define ESQ_OFF  131072       // 4096
#define ZSQ_OFF  135168       // 512
#define THR_OFF  135680       // 512
#define IDX_OFF  136192       // 512
#define SW_OFF   136704       // 32
#define SMEM_BYTES 136768
// post-GEMM window spill reuses EH region: [px][16 subs][4]
#define WD_OFF   EH_OFF               // 32768
#define WK_OFF   (EH_OFF + 32768)     // 32768

// Device scratch
__device__ uint32_t g_cbhT[128 * KCODES];   // transposed half2 codebook [c2][k]
__device__ float    g_esq[KCODES];
__device__ float    g_loss_acc;
__device__ int      g_esqmax_bits;

// ---- helpers ----
__device__ __forceinline__ uint32_t smem_u32(const void* p) {
    uint32_t a;
    asm("{ .reg .u64 t; cvta.to.shared.u64 t, %1; cvt.u32.u64 %0, t; }" : "=r"(a) : "l"(p));
    return a;
}
__device__ __forceinline__ uint32_t f16x2(float hi, float lo) {
    uint32_t r;
    asm("cvt.rn.f16x2.f32 %0, %1, %2;" : "=r"(r) : "f"(hi), "f"(lo));
    return r;
}
__device__ __forceinline__ float2 h2f(uint32_t h) {
    float lo, hi;
    asm("{ .reg .f16 l, u; mov.b32 {l, u}, %2;\n\t"
        "cvt.f32.f16 %0, l; cvt.f32.f16 %1, u; }" : "=f"(lo), "=f"(hi) : "r"(h));
    return make_float2(lo, hi);
}
#define HFMA2(d, a, b) \
    asm("fma.rn.f16x2 %0, %1, %2, %0;" : "+r"(d) : "r"(a), "r"(b))
#define CP_ASYNC16(dst, src) \
    asm volatile("cp.async.cg.shared.global [%0], [%1], 16;" :: "r"(dst), "l"(src))
#define CP_COMMIT  asm volatile("cp.async.commit_group;")
#define CP_WAIT1   asm volatile("cp.async.wait_group 1;")
#define CP_WAIT0   asm volatile("cp.async.wait_group 0;")

// 4-deep sorted window insert (guard rarely taken)
__device__ __forceinline__ void wins4(float d, int k, float* wd, int* wk) {
    if (d < wd[3]) {
        wd[3] = d; wk[3] = k;
        #pragma unroll
        for (int i = 3; i > 0; i--)
            if (wd[i] < wd[i - 1]) {
                float td = wd[i]; wd[i] = wd[i - 1]; wd[i - 1] = td;
                int   tk = wk[i]; wk[i] = wk[i - 1]; wk[i - 1] = tk;
            }
    }
}

// exact reference distance chain (z from global tile base, coalesced-ish, rare)
__device__ __forceinline__ float exact_dg(const float* __restrict__ zb, int px,
                                          float zsq, float eq,
                                          const float* __restrict__ cb, int k) {
    const float* e = cb + (size_t)k * DDIM;
    float dot = 0.0f;
    #pragma unroll 8
    for (int c = 0; c < DDIM; c++)
        dot = fmaf(__ldg(&zb[(size_t)c * HW + px]), __ldg(&e[c]), dot);
    return __fsub_rn(__fadd_rn(zsq, eq), __fmul_rn(2.0f, dot));
}

// ---------------------------------------------------------------------------
__global__ void vq_init() { g_loss_acc = 0.0f; g_esqmax_bits = 0; }

// prep: esq (exact sequential chain), esqmax, transposed half2 codebook
__global__ void vq_prep(const float* __restrict__ cb) {
    int k = blockIdx.x * blockDim.x + threadIdx.x;
    if (k >= KCODES) return;
    const float2* row = (const float2*)(cb + (size_t)k * DDIM);
    float s = 0.0f;
    #pragma unroll 8
    for (int c2 = 0; c2 < 128; c2++) {
        float2 v = row[c2];
        s = __fadd_rn(s, __fmul_rn(v.x, v.x));
        s = __fadd_rn(s, __fmul_rn(v.y, v.y));
        g_cbhT[c2 * KCODES + k] = f16x2(v.y, v.x);   // (lo=even c, hi=odd c)
    }
    g_esq[k] = s;
    atomicMax(&g_esqmax_bits, __float_as_int(s));    // s > 0 -> int cmp valid
}

// ---------------------------------------------------------------------------
__global__ __launch_bounds__(256, 1)
void vq_main(const float* __restrict__ z, const float* __restrict__ cb,
             float* __restrict__ out_zq, float* __restrict__ out_idx) {
    extern __shared__ char sm[];
    uint32_t* zh    = (uint32_t*)(sm + ZH_OFF);
    float*    esq_s = (float*)(sm + ESQ_OFF);
    float*    zsq_s = (float*)(sm + ZSQ_OFF);
    float*    thr_s = (float*)(sm + THR_OFF);
    int*      s_idx = (int*)(sm + IDX_OFF);
    float*    swsum = (float*)(sm + SW_OFF);
    const uint32_t smb = smem_u32(sm);

    const int t = threadIdx.x, tx = t & 15, ty = t >> 4, wid = t >> 5;
    const int tile = blockIdx.x, b = tile >> 5, hw0 = (tile & 31) << 7;
    const float* zb = z + (size_t)b * (DDIM * HW) + hw0;   // CTA z tile base

    // ---- issue cp.async for e-chunk 0 ----
    {
        const uint32_t* src = g_cbhT;
        uint32_t dstb = smb + EH_OFF;
        #pragma unroll
        for (int it = 0; it < 8; it++) {
            int task = it * 256 + t, c2 = task >> 4, seg = task & 15;
            CP_ASYNC16(dstb + c2 * 256 + seg * 16, src + c2 * KCODES + seg * 4);
        }
        CP_COMMIT;
    }

    // ---- quantize z -> zh half2 [c2][px] (coalesced LDG) ----
    #pragma unroll
    for (int it = 0; it < 16; it++) {
        int task = it * 256 + t, c2 = task >> 5, f4 = task & 31;
        float4 r0 = ((const float4*)(zb + (size_t)(2 * c2)     * HW))[f4];
        float4 r1 = ((const float4*)(zb + (size_t)(2 * c2 + 1) * HW))[f4];
        uint4 u;
        u.x = f16x2(r1.x, r0.x); u.y = f16x2(r1.y, r0.y);
        u.z = f16x2(r1.z, r0.z); u.w = f16x2(r1.w, r0.w);
        *(uint4*)(zh + c2 * 128 + f4 * 4) = u;
    }

    // ---- zsq (exact sequential chain, coalesced global re-read) | esq stage ----
    float emax = __int_as_float(g_esqmax_bits);
    if (t < TILE_PX) {
        int px = t;
        float s = 0.0f;
        #pragma unroll 8
        for (int c = 0; c < DDIM; c++) {
            float v = __ldg(&zb[(size_t)c * HW + px]);
            s = __fadd_rn(s, __fmul_rn(v, v));
        }
        zsq_s[px] = s;
        // provable fp16 bound: eps_d = 2 * S * (2 + 128) * 2^-11, S = sqrt(zsq*esqmax)
        // thr margin = 2*eps_d <= 0.254*S; use 0.26*S + slop for fp32-chain noise
        thr_s[px] = 0.26f * sqrtf(s * emax) + 3e-4f;
    } else {
        int i = t - 128;
        ((uint4*)esq_s)[i]       = ((const uint4*)g_esq)[i];
        ((uint4*)esq_s)[i + 128] = ((const uint4*)g_esq)[i + 128];
    }

    // ---- GEMM: 16 chunks x 64 codes, HFMA2, cp.async double-buffered ----
    float wd[8][4]; int wk[8][4];
    #pragma unroll
    for (int i = 0; i < 8; i++)
        #pragma unroll
        for (int w = 0; w < 4; w++) { wd[i][w] = 3.4e38f; wk[i][w] = 0; }

    const uint32_t* zhp = zh + ty * 8;

    for (int n = 0; n < NCHUNK; n++) {
        if (n + 1 < NCHUNK) {
            const uint32_t* src = g_cbhT + (n + 1) * CHUNK;
            uint32_t dstb = smb + EH_OFF + (uint32_t)((n + 1) & 1) * EH_BYTES;
            #pragma unroll
            for (int it = 0; it < 8; it++) {
                int task = it * 256 + t, c2 = task >> 4, seg = task & 15;
                CP_ASYNC16(dstb + c2 * 256 + seg * 16, src + c2 * KCODES + seg * 4);
            }
            CP_COMMIT;
            CP_WAIT1;
        } else {
            CP_WAIT0;
        }
        __syncthreads();   // chunk n data + (n==0: zh/zsq/esq) visible

        const uint32_t* eh = (const uint32_t*)(sm + EH_OFF + (n & 1) * EH_BYTES);
        uint32_t acc[8][4];
        #pragma unroll
        for (int i = 0; i < 8; i++)
            acc[i][0] = acc[i][1] = acc[i][2] = acc[i][3] = 0u;

        #pragma unroll 4
        for (int c2 = 0; c2 < 128; c2++) {
            uint4 za = *(const uint4*)(zhp + c2 * 128);
            uint4 zc = *(const uint4*)(zhp + c2 * 128 + 4);
            uint32_t e0 = eh[c2 * 64 + tx];
            uint32_t e1 = eh[c2 * 64 + tx + 16];
            uint32_t e2 = eh[c2 * 64 + tx + 32];
            uint32_t e3 = eh[c2 * 64 + tx + 48];
            uint32_t zp[8] = {za.x, za.y, za.z, za.w, zc.x, zc.y, zc.z, zc.w};
            #pragma unroll
            for (int i = 0; i < 8; i++) {
                HFMA2(acc[i][0], zp[i], e0);
                HFMA2(acc[i][1], zp[i], e1);
                HFMA2(acc[i][2], zp[i], e2);
                HFMA2(acc[i][3], zp[i], e3);
            }
        }

        // distances + window update
        #pragma unroll
        for (int j = 0; j < 4; j++) {
            int kg = n * CHUNK + tx + 16 * j;
            float eq = esq_s[kg];
            #pragma unroll
            for (int i = 0; i < 8; i++) {
                float2 f = h2f(acc[i][j]);
                float d = fmaf(-2.0f, f.x + f.y, eq);
                wins4(d, kg, wd[i], wk[i]);
            }
        }
        __syncthreads();   // all reads of eh[n&1] done before next cp.async writes it
    }

    // ---- spill windows: [px][16 subs][4] (reuses dead eh region) ----
    float* WD = (float*)(sm + WD_OFF);
    int*   WK = (int*)(sm + WK_OFF);
    #pragma unroll
    for (int i = 0; i < 8; i++) {
        int px = ty * 8 + i;
        #pragma unroll
        for (int w = 0; w < 4; w++) {
            WD[(px * 16 + tx) * 4 + w] = wd[i][w];
            WK[(px * 16 + tx) * 4 + w] = wk[i][w];
        }
    }
    __syncthreads();

    // ---- resolution: certify or exact-recheck ----
    if (t < TILE_PX) {
        int px = t;
        float zsq = zsq_s[px];
        float m0 = 3.4e38f, m1 = 3.4e38f; int k0 = 0;
        #pragma unroll 8
        for (int e = 0; e < 64; e++) {
            float dv = WD[px * 64 + e];
            if (dv < m0) { m1 = m0; m0 = dv; k0 = WK[px * 64 + e]; }
            else if (dv < m1) m1 = dv;
        }
        float thr = m0 + thr_s[px];
        int kb;
        if (m1 > thr) {
            kb = k0;                                    // provably the exact argmin
        } else {
            float bd = 3.4e38f; kb = 0x7FFFFFFF;
            #pragma unroll 1
            for (int s = 0; s < 16; s++) {
                const float* wdp = WD + px * 64 + s * 4;
                const int*   wkp = WK + px * 64 + s * 4;
                if (wdp[3] <= thr) {
                    // sub window overflow (rare): exact-scan sub's 64 codes, 4-way ILP
                    #pragma unroll 1
                    for (int mg = 0; mg < 16; mg++) {
                        int ks = (mg * 4) * 16 + s;
                        const float* e0 = cb + (size_t)(ks)      * DDIM;
                        const float* e1 = cb + (size_t)(ks + 16) * DDIM;
                        const float* e2 = cb + (size_t)(ks + 32) * DDIM;
                        const float* e3 = cb + (size_t)(ks + 48) * DDIM;
                        float d0 = 0, d1 = 0, d2 = 0, d3 = 0;
                        #pragma unroll 4
                        for (int c = 0; c < DDIM; c++) {
                            float zv = __ldg(&zb[(size_t)c * HW + px]);
                            d0 = fmaf(zv, __ldg(&e0[c]), d0);
                            d1 = fmaf(zv, __ldg(&e1[c]), d1);
                            d2 = fmaf(zv, __ldg(&e2[c]), d2);
                            d3 = fmaf(zv, __ldg(&e3[c]), d3);
                        }
                        float dx[4] = {d0, d1, d2, d3};
                        #pragma unroll
                        for (int j = 0; j < 4; j++) {
                            int k = ks + 16 * j;
                            float dex = __fsub_rn(__fadd_rn(zsq, esq_s[k]),
                                                  __fmul_rn(2.0f, dx[j]));
                            if (dex < bd || (dex == bd && k < kb)) { bd = dex; kb = k; }
                        }
                    }
                } else {
                    #pragma unroll 1
                    for (int w = 0; w < 4; w++)
                        if (wdp[w] <= thr) {
                            int k = wkp[w];
                            float dex = exact_dg(zb, px, zsq, esq_s[k], cb, k);
                            if (dex < bd || (dex == bd && k < kb)) { bd = dex; kb = k; }
                        }
                }
            }
        }
        s_idx[px] = kb;
        out_idx[(size_t)tile * TILE_PX + px] = (float)kb;
    }
    __syncthreads();

    // ---- epilogue: straight-through z_q + loss (bit-exact chains, coalesced) ----
    float lsum = 0.0f;
    float* out_base = out_zq + (size_t)b * (DDIM * HW) + hw0;
    #pragma unroll 4
    for (int r = 0; r < 128; r++) {
        int e = r * 256 + t, c = e >> 7, px = e & 127;
        int kk = s_idx[px];
        float q  = __ldg(&cb[(size_t)kk * DDIM + c]);
        float zv = __ldg(&zb[(size_t)c * HW + px]);
        float dd = __fsub_rn(q, zv);
        lsum = fmaf(dd, dd, lsum);
        out_base[(size_t)c * HW + px] = __fadd_rn(zv, dd);
    }

    #pragma unroll
    for (int off = 16; off >= 1; off >>= 1)
        lsum += __shfl_xor_sync(0xFFFFFFFFu, lsum, off);
    if ((t & 31) == 0) swsum[wid] = lsum;
    __syncthreads();
    if (t == 0) {
        float bs = 0.0f;
        #pragma unroll
        for (int w = 0; w < 8; w++) bs += swsum[w];
        atomicAdd(&g_loss_acc, bs);
    }
}

// ---------------------------------------------------------------------------
__global__ void vq_finalize(float* __restrict__ out) {
    float m = __fmul_rn(g_loss_acc, 1.0f / (float)ZQ_ELEMS);
    out[ZQ_ELEMS + NPX] = __fmul_rn(1.25f, m);
}

extern "C" void kernel_launch(void* const* d_in, const int* in_sizes, int n_in,
                              void* d_out, int out_size) {
    const float* z  = (const float*)d_in[0];
    const float* cb = (const float*)d_in[1];
    float* out = (float*)d_out;
    float* out_zq  = out;
    float* out_idx = out + ZQ_ELEMS;

    vq_init<<<1, 1>>>();
    vq_prep<<<4, 256>>>(cb);

    cudaFuncSetAttribute(vq_main, cudaFuncAttributeMaxDynamicSharedMemorySize, SMEM_BYTES);
    vq_main<<<NPX / TILE_PX, 256, SMEM_BYTES>>>(z, cb, out_zq, out_idx);

    vq_finalize<<<1, 1>>>(out);
}

// round 8
// speedup vs baseline: 14.9866x; 14.9866x over previous
#include <cuda_runtime.h>

// Problem constants
#define NPX      65536      // 16 * 64 * 64 pixels
#define KCODES   1024
#define DDIM     256
#define HW       4096       // 64*64
#define TILE_PX  64
#define TILE_K   128
#define NKT      (KCODES / TILE_K)   // 8
#define NTILES   (NPX / TILE_PX)     // 1024
#define ZQ_ELEMS 16777216   // 16*256*64*64

// Scratch (device globals; allocation-free per harness rules)
__device__ float g_esq[KCODES];
__device__ float g_loss_acc;

// smem layout (floats):
//   z_s   [256][64]             16384
//   e_s   [128][257]            32896   (257 pad -> conflict-free compute reads)
//   esq_s [1024]                 1024
//   zsq_s [64]                     64
//   s_idx [64] (as int)            64
//   swsum [8]                       8
#define ZS_F   (DDIM * TILE_PX)          // 16384
#define ES_F   (TILE_K * 257)            // 32896
#define ESQ_F  ZS_F + ES_F
#define SMEM_FLOATS (ZS_F + ES_F + 1024 + 64 + 64 + 8)

// ---------------------------------------------------------------------------
// Prep: esq[k] = sequential fp32 sum of e_c^2 (mul then add); zero loss acc.
// ---------------------------------------------------------------------------
__global__ void vq_prep(const float* __restrict__ cb) {
    int k = blockIdx.x * blockDim.x + threadIdx.x;
    if (k == 0) g_loss_acc = 0.0f;
    if (k < KCODES) {
        const float* row = cb + (size_t)k * DDIM;
        float s = 0.0f;
        #pragma unroll 8
        for (int c = 0; c < DDIM; c++) {
            float v = row[c];
            s = __fadd_rn(s, __fmul_rn(v, v));   // sequential, no FMA contraction
        }
        g_esq[k] = s;
    }
}

// ---------------------------------------------------------------------------
// Main: fused distance-GEMM + argmin + z_q gather/write + loss partial.
// 64-px tiles (grid 1024) to cut wave-quantization tail from 16% to 3.9%.
// ---------------------------------------------------------------------------
__global__ __launch_bounds__(256, 1)
void vq_main(const float* __restrict__ z, const float* __restrict__ cb,
             float* __restrict__ out_zq, float* __restrict__ out_idx) {
    extern __shared__ float smem[];
    float* z_s   = smem;
    float* e_s   = smem + ZS_F;
    float* esq_s = smem + ZS_F + ES_F;
    float* zsq_s = smem + ZS_F + ES_F + 1024;
    int*   s_idx = (int*)(smem + ZS_F + ES_F + 1024 + 64);
    float* swsum = smem + ZS_F + ES_F + 1024 + 128;

    const int t  = threadIdx.x;
    const int tx = t & 31;        // code lane (32 codes x 4 groups)
    const int ty = t >> 5;        // warp id == pixel group (8 px each)
    const int tile = blockIdx.x;            // 0..1023
    const int b    = tile >> 6;             // batch index (64 tiles per batch)
    const int hw0  = (tile & 63) << 6;      // hw offset (contiguous 64 pixels)

    const float* zb = z + (size_t)b * (DDIM * HW) + hw0;

    // Load z tile [256 c][64 px] into smem (coalesced: hw is fast axis)
    #pragma unroll
    for (int r = 0; r < 16; r++) {
        int e  = r * 256 + t;     // float4 task id, 4096 total
        int c  = e >> 4;
        int f4 = e & 15;
        float4 v = ((const float4*)(zb + (size_t)c * HW))[f4];
        *((float4*)&z_s[c * TILE_PX + f4 * 4]) = v;
    }
    // esq -> smem (1024 floats = 256 float4)
    ((float4*)esq_s)[t] = ((const float4*)g_esq)[t];
    __syncthreads();

    // Per-pixel zsq: sequential fp32 sum of z_c^2 (mul then add, exact chain)
    if (t < TILE_PX) {
        float s = 0.0f;
        for (int c = 0; c < DDIM; c++) {
            float v = z_s[c * TILE_PX + t];
            s = __fadd_rn(s, __fmul_rn(v, v));
        }
        zsq_s[t] = s;
    }
    __syncthreads();

    float zsqr[8];
    #pragma unroll
    for (int i = 0; i < 8; i++) zsqr[i] = zsq_s[ty * 8 + i];

    float bestd[8];
    int   bestk[8];
    #pragma unroll
    for (int i = 0; i < 8; i++) { bestd[i] = 3.4e38f; bestk[i] = 0; }

    for (int kt = 0; kt < NKT; kt++) {
        if (kt) __syncthreads();
        // Load codebook tile [128 k][256 c] -> e_s[k*257 + c]
        const float* cbt = cb + (size_t)kt * TILE_K * DDIM;
        #pragma unroll
        for (int i = 0; i < 32; i++) {
            int e  = i * 256 + t;     // 8192 float4 tasks
            int k  = e >> 6;
            int c4 = e & 63;
            float4 v = ((const float4*)(cbt + k * DDIM))[c4];
            float* dst = &e_s[k * 257 + c4 * 4];
            dst[0] = v.x; dst[1] = v.y; dst[2] = v.z; dst[3] = v.w;
        }
        __syncthreads();

        float acc[8][4];
        #pragma unroll
        for (int i = 0; i < 8; i++)
            #pragma unroll
            for (int j = 0; j < 4; j++) acc[i][j] = 0.0f;

        // dot products: 8 px x 4 codes per thread.
        // Single accumulator per element, ascending c, fused FMA chain
        // (bit-identical to the proven round-2 ordering).
        #pragma unroll 8
        for (int c = 0; c < DDIM; c++) {
            float4 za  = *((const float4*)&z_s[c * TILE_PX + ty * 8]);      // broadcast
            float4 zb4 = *((const float4*)&z_s[c * TILE_PX + ty * 8 + 4]);  // broadcast
            float rz0 = za.x, rz1 = za.y, rz2 = za.z, rz3 = za.w;
            float rz4 = zb4.x, rz5 = zb4.y, rz6 = zb4.z, rz7 = zb4.w;
            float re[4];
            #pragma unroll
            for (int j = 0; j < 4; j++)
                re[j] = e_s[(tx + 32 * j) * 257 + c];   // conflict-free: bank = tx+c
            #pragma unroll
            for (int j = 0; j < 4; j++) {
                acc[0][j] = fmaf(rz0, re[j], acc[0][j]);
                acc[1][j] = fmaf(rz1, re[j], acc[1][j]);
                acc[2][j] = fmaf(rz2, re[j], acc[2][j]);
                acc[3][j] = fmaf(rz3, re[j], acc[3][j]);
                acc[4][j] = fmaf(rz4, re[j], acc[4][j]);
                acc[5][j] = fmaf(rz5, re[j], acc[5][j]);
                acc[6][j] = fmaf(rz6, re[j], acc[6][j]);
                acc[7][j] = fmaf(rz7, re[j], acc[7][j]);
            }
        }

        // d = fl( fl(zsq + esq_k) - fl(2*dot) )   -- exact reference rounding.
        // k visited ascending per thread -> strict < keeps first-min.
        #pragma unroll
        for (int j = 0; j < 4; j++) {
            int kg = kt * TILE_K + tx + 32 * j;
            float eq = esq_s[kg];
            #pragma unroll
            for (int i = 0; i < 8; i++) {
                float t1 = __fadd_rn(zsqr[i], eq);
                float d  = __fsub_rn(t1, __fmul_rn(2.0f, acc[i][j]));
                if (d < bestd[i]) { bestd[i] = d; bestk[i] = kg; }
            }
        }
    }

    // Full-warp butterfly min-reduce with lowest-index tie-break
    #pragma unroll
    for (int i = 0; i < 8; i++) {
        float d = bestd[i];
        int   k = bestk[i];
        #pragma unroll
        for (int off = 16; off >= 1; off >>= 1) {
            float od = __shfl_xor_sync(0xFFFFFFFFu, d, off);
            int   ok = __shfl_xor_sync(0xFFFFFFFFu, k, off);
            if (od < d || (od == d && ok < k)) { d = od; k = ok; }
        }
        if (tx == 0) s_idx[ty * 8 + i] = k;
    }
    __syncthreads();

    // Epilogue: straight-through z_q write (coalesced), loss partial, idx write
    float lsum = 0.0f;
    float* out_base = out_zq + (size_t)b * (DDIM * HW) + hw0;
    #pragma unroll 4
    for (int r = 0; r < 64; r++) {
        int e  = r * 256 + t;       // 16384 elements
        int c  = e >> 6;
        int px = e & 63;
        int kk = s_idx[px];
        float q  = __ldg(&cb[(size_t)kk * DDIM + c]);
        float zv = z_s[c * TILE_PX + px];
        float dd = __fsub_rn(q, zv);                 // z_q - z
        lsum = fmaf(dd, dd, lsum);                   // loss partial
        out_base[(size_t)c * HW + px] = __fadd_rn(zv, dd);  // z + (z_q - z)
    }
    if (t < TILE_PX) out_idx[(size_t)tile * TILE_PX + t] = (float)s_idx[t];

    // block loss reduce
    #pragma unroll
    for (int off = 16; off >= 1; off >>= 1)
        lsum += __shfl_xor_sync(0xFFFFFFFFu, lsum, off);
    if ((t & 31) == 0) swsum[t >> 5] = lsum;
    __syncthreads();
    if (t == 0) {
        float bs = 0.0f;
        #pragma unroll
        for (int w = 0; w < 8; w++) bs += swsum[w];
        atomicAdd(&g_loss_acc, bs);
    }
}

// ---------------------------------------------------------------------------
// Finalize: loss = mean + BETA*mean = 1.25 * (sum / 2^24)
// ---------------------------------------------------------------------------
__global__ void vq_finalize(float* __restrict__ out) {
    float m = __fmul_rn(g_loss_acc, 1.0f / (float)ZQ_ELEMS);  // /2^24 exact
    out[ZQ_ELEMS + NPX] = __fmul_rn(1.25f, m);
}

extern "C" void kernel_launch(void* const* d_in, const int* in_sizes, int n_in,
                              void* d_out, int out_size) {
    const float* z  = (const float*)d_in[0];
    const float* cb = (const float*)d_in[1];
    float* out = (float*)d_out;

    // out layout: [z_q: 16777216][idx: 65536][loss: 1]
    float* out_zq  = out;
    float* out_idx = out + ZQ_ELEMS;

    vq_prep<<<8, 128>>>(cb);

    size_t smem_bytes = SMEM_FLOATS * sizeof(float);
    cudaFuncSetAttribute(vq_main, cudaFuncAttributeMaxDynamicSharedMemorySize,
                         (int)smem_bytes);
    vq_main<<<NTILES, 256, smem_bytes>>>(z, cb, out_zq, out_idx);

    vq_finalize<<<1, 1>>>(out);
}